// round 13
// baseline (speedup 1.0000x reference)
#include <cuda_runtime.h>
#include <cuda_bf16.h>
#include <mma.h>
#include <cstdint>

using namespace nvcuda;

// Problem dims (fixed)
#define BB   64
#define TT   512
#define IDIM 256
#define HH   512
#define BTH  (BB*TT*HH)

// Recurrence decomposition: 16 clusters (batch groups) x 8 CTAs (column groups)
#define GB   16
#define GC   8
#define BPG  4
#define CPG  64
#define NCTA (GB*GC)
#define THR  256
#define NWORK 16                 // in-grid gemm1 worker CTAs (2 clusters)
#define NTILES 4096              // gemm1 tiles: 8 tchunks x 64 b x 8 nb

// ------------------------------ scratch ------------------------------------
__device__ float g_xb[TT*BB*HH];              // input projection [t][b][h]
__device__ __nv_bfloat16 g_ahi[BTH];          // layer-0 output, split hi
__device__ __nv_bfloat16 g_alo[BTH];          // layer-0 output, split lo
__device__ __nv_bfloat16 g_whi0[HH*IDIM];
__device__ __nv_bfloat16 g_wlo0[HH*IDIM];
__device__ __nv_bfloat16 g_whi1[HH*HH];
__device__ __nv_bfloat16 g_wlo1[HH*HH];
__device__ unsigned g_prog[GB*GC];            // rec0 progress per CTA
__device__ unsigned g_tile;                   // gemm1 tile queue head
__device__ unsigned g_done;                   // rec0 CTAs finished

// ------------------------------ split conversion -----------------------------
__global__ void conv_split(const float* __restrict__ s,
                           __nv_bfloat16* __restrict__ hi,
                           __nv_bfloat16* __restrict__ lo, int n, int rst)
{
    int i = blockIdx.x * blockDim.x + threadIdx.x;
    if (rst && blockIdx.x == 0) {
        if (threadIdx.x < GB*GC) g_prog[threadIdx.x] = 0u;
        if (threadIdx.x == 128)  g_tile = 0u;
        if (threadIdx.x == 129)  g_done = 0u;
    }
    if (i < n) {
        float x = s[i];
        __nv_bfloat16 h = __float2bfloat16_rn(x);
        hi[i] = h;
        lo[i] = __float2bfloat16_rn(x - __bfloat162float(h));
    }
}

// ------------------------------ gemm helpers ---------------------------------
#define KC   64
#define LDS2 72

__device__ __forceinline__ void split16_store(
    const float* __restrict__ srcf, __nv_bfloat16* dH16, __nv_bfloat16* dL16)
{
    const float4* src = reinterpret_cast<const float4*>(srcf);
    float v[16];
#pragma unroll
    for (int j = 0; j < 4; ++j) {
        float4 f = src[j];
        v[j*4+0] = f.x; v[j*4+1] = f.y; v[j*4+2] = f.z; v[j*4+3] = f.w;
    }
    uint32_t ph[8], pl[8];
#pragma unroll
    for (int i = 0; i < 8; ++i) {
        __nv_bfloat16 h0b = __float2bfloat16_rn(v[2*i]);
        __nv_bfloat16 h1b = __float2bfloat16_rn(v[2*i+1]);
        __nv_bfloat16 l0b = __float2bfloat16_rn(v[2*i]   - __bfloat162float(h0b));
        __nv_bfloat16 l1b = __float2bfloat16_rn(v[2*i+1] - __bfloat162float(h1b));
        ph[i] = (uint32_t)__bfloat16_as_ushort(h0b) |
                ((uint32_t)__bfloat16_as_ushort(h1b) << 16);
        pl[i] = (uint32_t)__bfloat16_as_ushort(l0b) |
                ((uint32_t)__bfloat16_as_ushort(l1b) << 16);
    }
    uint4* dH = reinterpret_cast<uint4*>(dH16);
    uint4* dL = reinterpret_cast<uint4*>(dL16);
    dH[0] = make_uint4(ph[0],ph[1],ph[2],ph[3]);
    dH[1] = make_uint4(ph[4],ph[5],ph[6],ph[7]);
    dL[0] = make_uint4(pl[0],pl[1],pl[2],pl[3]);
    dL[1] = make_uint4(pl[4],pl[5],pl[6],pl[7]);
}

// ------------------------------ gemm0 (fp32 A fused split, pre-split B) ------
__global__ void __launch_bounds__(256) gemm_wmma(
    const float* __restrict__ Afp,
    const __nv_bfloat16* __restrict__ Bh, const __nv_bfloat16* __restrict__ Bl,
    const float* __restrict__ b1, const float* __restrict__ b2, int K)
{
    __shared__ char raw[4 * 64 * LDS2 * 2];
    __nv_bfloat16* sAh = reinterpret_cast<__nv_bfloat16*>(raw);
    __nv_bfloat16* sAl = sAh + 64 * LDS2;
    __nv_bfloat16* sBh = sAl + 64 * LDS2;
    __nv_bfloat16* sBl = sBh + 64 * LDS2;

    const int tid = threadIdx.x;
    const int nb  = blockIdx.x;
    const int mb  = blockIdx.y;
    const int wid = tid >> 5;
    const int wr  = wid & 3;
    const int wc  = wid >> 2;

    wmma::fragment<wmma::accumulator, 16, 16, 16, float> acc[2];
    wmma::fill_fragment(acc[0], 0.0f);
    wmma::fill_fragment(acc[1], 0.0f);

    const int row = tid >> 2;
    const int seg = (tid & 3) * 16;

    for (int k0 = 0; k0 < K; k0 += KC) {
        __syncthreads();
        split16_store(Afp + (size_t)(mb*64 + row)*K + k0 + seg,
                      sAh + row*LDS2 + seg, sAl + row*LDS2 + seg);
        {
            const uint4* b_h = reinterpret_cast<const uint4*>(Bh + (size_t)(nb*64 + row)*K + k0 + seg);
            const uint4* b_l = reinterpret_cast<const uint4*>(Bl + (size_t)(nb*64 + row)*K + k0 + seg);
            uint4* dH = reinterpret_cast<uint4*>(sBh + row*LDS2 + seg);
            uint4* dL = reinterpret_cast<uint4*>(sBl + row*LDS2 + seg);
            dH[0] = b_h[0]; dH[1] = b_h[1];
            dL[0] = b_l[0]; dL[1] = b_l[1];
        }
        __syncthreads();

#pragma unroll
        for (int kk = 0; kk < KC / 16; ++kk) {
            wmma::fragment<wmma::matrix_a, 16, 16, 16, __nv_bfloat16, wmma::row_major> fa_h, fa_l;
            wmma::load_matrix_sync(fa_h, sAh + (wr*16)*LDS2 + kk*16, LDS2);
            wmma::load_matrix_sync(fa_l, sAl + (wr*16)*LDS2 + kk*16, LDS2);
#pragma unroll
            for (int ns = 0; ns < 2; ++ns) {
                wmma::fragment<wmma::matrix_b, 16, 16, 16, __nv_bfloat16, wmma::col_major> fb_h, fb_l;
                wmma::load_matrix_sync(fb_h, sBh + (wc*32 + ns*16)*LDS2 + kk*16, LDS2);
                wmma::load_matrix_sync(fb_l, sBl + (wc*32 + ns*16)*LDS2 + kk*16, LDS2);
                wmma::mma_sync(acc[ns], fa_h, fb_h, acc[ns]);
                wmma::mma_sync(acc[ns], fa_h, fb_l, acc[ns]);
                wmma::mma_sync(acc[ns], fa_l, fb_h, acc[ns]);
            }
        }
    }

    __syncthreads();
    float* Cs = reinterpret_cast<float*>(raw);
    wmma::store_matrix_sync(Cs + (wr*16)*LDS2 + wc*32 + 0,  acc[0], LDS2, wmma::mem_row_major);
    wmma::store_matrix_sync(Cs + (wr*16)*LDS2 + wc*32 + 16, acc[1], LDS2, wmma::mem_row_major);
    __syncthreads();

    const int col4 = (tid & 15) * 4;
    const int n0   = nb * 64 + col4;
    float4 bias;
    bias.x = b1[n0 + 0] + b2[n0 + 0];
    bias.y = b1[n0 + 1] + b2[n0 + 1];
    bias.z = b1[n0 + 2] + b2[n0 + 2];
    bias.w = b1[n0 + 3] + b2[n0 + 3];

#pragma unroll
    for (int rr = 0; rr < 4; ++rr) {
        int r  = rr * 16 + (tid >> 4);
        int m  = mb * 64 + r;
        int b_ = m >> 9;
        int t_ = m & (TT - 1);
        float4 o;
        o.x = Cs[r * LDS2 + col4 + 0] + bias.x;
        o.y = Cs[r * LDS2 + col4 + 1] + bias.y;
        o.z = Cs[r * LDS2 + col4 + 2] + bias.z;
        o.w = Cs[r * LDS2 + col4 + 3] + bias.w;
        *reinterpret_cast<float4*>(&g_xb[((size_t)t_ * BB + b_) * HH + n0]) = o;
    }
}

// ------------------------------ gemm1 tile body ------------------------------
// Computes one 64x64 tile of layer-1 input projection from pre-split bf16
// activations (g_ahi/g_alo) x weights (g_whi1/g_wlo1), writes g_xb.
__device__ void gemm1_tile_compute(int tile, char* raw, int tid,
                                   const float* __restrict__ b1,
                                   const float* __restrict__ b2)
{
    __nv_bfloat16* sAh = reinterpret_cast<__nv_bfloat16*>(raw);
    __nv_bfloat16* sAl = sAh + 64 * LDS2;
    __nv_bfloat16* sBh = sAl + 64 * LDS2;
    __nv_bfloat16* sBl = sBh + 64 * LDS2;

    const int wid = tid >> 5;
    const int wr  = wid & 3;
    const int wc  = wid >> 2;
    const int row = tid >> 2;
    const int seg = (tid & 3) * 16;
    const int K   = HH;

    const int tchunk = tile >> 9;
    const int rest   = tile & 511;
    const int b      = rest >> 3;
    const int nb     = rest & 7;
    const int m0     = b * TT + tchunk * 64;

    wmma::fragment<wmma::accumulator, 16, 16, 16, float> acc[2];
    wmma::fill_fragment(acc[0], 0.0f);
    wmma::fill_fragment(acc[1], 0.0f);

    for (int k0 = 0; k0 < K; k0 += KC) {
        __syncthreads();
        {
            const int4* a_h = reinterpret_cast<const int4*>(g_ahi + (size_t)(m0 + row)*K + k0 + seg);
            const int4* a_l = reinterpret_cast<const int4*>(g_alo + (size_t)(m0 + row)*K + k0 + seg);
            int4* dH = reinterpret_cast<int4*>(sAh + row*LDS2 + seg);
            int4* dL = reinterpret_cast<int4*>(sAl + row*LDS2 + seg);
            dH[0] = __ldcg(a_h + 0); dH[1] = __ldcg(a_h + 1);
            dL[0] = __ldcg(a_l + 0); dL[1] = __ldcg(a_l + 1);
        }
        {
            const int4* b_h = reinterpret_cast<const int4*>(g_whi1 + (size_t)(nb*64 + row)*K + k0 + seg);
            const int4* b_l = reinterpret_cast<const int4*>(g_wlo1 + (size_t)(nb*64 + row)*K + k0 + seg);
            int4* dH = reinterpret_cast<int4*>(sBh + row*LDS2 + seg);
            int4* dL = reinterpret_cast<int4*>(sBl + row*LDS2 + seg);
            dH[0] = b_h[0]; dH[1] = b_h[1];
            dL[0] = b_l[0]; dL[1] = b_l[1];
        }
        __syncthreads();

#pragma unroll
        for (int kk = 0; kk < KC / 16; ++kk) {
            wmma::fragment<wmma::matrix_a, 16, 16, 16, __nv_bfloat16, wmma::row_major> fa_h, fa_l;
            wmma::load_matrix_sync(fa_h, sAh + (wr*16)*LDS2 + kk*16, LDS2);
            wmma::load_matrix_sync(fa_l, sAl + (wr*16)*LDS2 + kk*16, LDS2);
#pragma unroll
            for (int ns = 0; ns < 2; ++ns) {
                wmma::fragment<wmma::matrix_b, 16, 16, 16, __nv_bfloat16, wmma::col_major> fb_h, fb_l;
                wmma::load_matrix_sync(fb_h, sBh + (wc*32 + ns*16)*LDS2 + kk*16, LDS2);
                wmma::load_matrix_sync(fb_l, sBl + (wc*32 + ns*16)*LDS2 + kk*16, LDS2);
                wmma::mma_sync(acc[ns], fa_h, fb_h, acc[ns]);
                wmma::mma_sync(acc[ns], fa_h, fb_l, acc[ns]);
                wmma::mma_sync(acc[ns], fa_l, fb_h, acc[ns]);
            }
        }
    }

    __syncthreads();
    float* Cs = reinterpret_cast<float*>(raw);
    wmma::store_matrix_sync(Cs + (wr*16)*LDS2 + wc*32 + 0,  acc[0], LDS2, wmma::mem_row_major);
    wmma::store_matrix_sync(Cs + (wr*16)*LDS2 + wc*32 + 16, acc[1], LDS2, wmma::mem_row_major);
    __syncthreads();

    const int col4 = (tid & 15) * 4;
    const int n0   = nb * 64 + col4;
    float4 bias;
    bias.x = b1[n0 + 0] + b2[n0 + 0];
    bias.y = b1[n0 + 1] + b2[n0 + 1];
    bias.z = b1[n0 + 2] + b2[n0 + 2];
    bias.w = b1[n0 + 3] + b2[n0 + 3];

#pragma unroll
    for (int rr = 0; rr < 4; ++rr) {
        int r  = rr * 16 + (tid >> 4);
        int m  = m0 + r;
        int b_ = m >> 9;
        int t_ = m & (TT - 1);
        float4 o;
        o.x = Cs[r * LDS2 + col4 + 0] + bias.x;
        o.y = Cs[r * LDS2 + col4 + 1] + bias.y;
        o.z = Cs[r * LDS2 + col4 + 2] + bias.z;
        o.w = Cs[r * LDS2 + col4 + 3] + bias.w;
        *reinterpret_cast<float4*>(&g_xb[((size_t)t_ * BB + b_) * HH + n0]) = o;
    }
}

// ------------------------------ cleanup: drain remaining tiles ---------------
__global__ void __launch_bounds__(256) gemm1_cleanup(
    const float* __restrict__ b1, const float* __restrict__ b2)
{
    __shared__ char raw[4 * 64 * LDS2 * 2];
    __shared__ int s_tile;
    const int tid = threadIdx.x;
    for (;;) {
        __syncthreads();
        if (tid == 0) s_tile = (int)atomicAdd(&g_tile, 1u);
        __syncthreads();
        if (s_tile >= NTILES) break;
        gemm1_tile_compute(s_tile, raw, tid, b1, b2);
    }
}

// ------------------------------ helpers -------------------------------------
__device__ __forceinline__ uint32_t smem_u32(const void* p) {
    uint32_t a;
    asm("{ .reg .u64 t; cvta.to.shared.u64 t, %1; cvt.u32.u64 %0, t; }"
        : "=r"(a) : "l"(p));
    return a;
}

__device__ __forceinline__ void mbar_wait(uint32_t mbar, uint32_t parity) {
    asm volatile(
        "{\n\t"
        ".reg .pred P;\n\t"
        "WL%=:\n\t"
        "mbarrier.try_wait.parity.acquire.cluster.shared::cta.b64 P, [%0], %1;\n\t"
        "@!P bra WL%=;\n\t"
        "}"
        :: "r"(mbar), "r"(parity) : "memory");
}

// ------------------------------ recurrence + in-grid gemm1 workers ----------
#define SM_W    (HH*CPG)
#define SM_HB   (SM_W)
#define SM_RED  (SM_W + 2*BPG*HH)
#define SM_MBAR (SM_RED + 16*256)
#define REC_SMEM_BYTES ((SM_MBAR + 8) * 4)

#define STEP_TX (GC * 256 * 4)

__global__ void __launch_bounds__(THR, 1) __cluster_dims__(GC, 1, 1)
rec_fused(const float* __restrict__ Whh,
          const float* __restrict__ h0,
          float* __restrict__ out_param,
          float* __restrict__ hn,
          int use_g0out,
          const float* __restrict__ g1b1,   // layer-1 biases for workers
          const float* __restrict__ g1b2)
{
    extern __shared__ float sm[];
    __shared__ int s_tile;
    const int tid = threadIdx.x;

    // ================= worker clusters (blockIdx.x >= NCTA) =================
    if (blockIdx.x >= NCTA) {
        char* raw = reinterpret_cast<char*>(sm);
        for (;;) {
            __syncthreads();
            if (tid == 0) {
                unsigned dn = *(volatile unsigned*)&g_done;
                s_tile = (dn >= (unsigned)NCTA) ? NTILES
                                                : (int)atomicAdd(&g_tile, 1u);
            }
            __syncthreads();
            const int tile = s_tile;
            if (tile >= NTILES) break;

            // Spin until rec0 published the needed steps for this tile.
            const int tchunk = tile >> 9;
            const int b      = (tile & 511) >> 3;
            if (tid < GC) {
                const unsigned target = (unsigned)((tchunk + 1) * 64);
                const unsigned* pp = &g_prog[(b >> 2) * GC + tid];
                unsigned v;
                for (;;) {
                    asm volatile("ld.acquire.gpu.global.u32 %0, [%1];"
                                 : "=r"(v) : "l"(pp) : "memory");
                    if (v >= target) break;
                    __nanosleep(200);
                }
            }
            __syncthreads();

            gemm1_tile_compute(tile, raw, tid, g1b1, g1b2);
        }
        return;
    }

    // ================= rec clusters (proven R10/R11 core) ===================
    float* Wt  = sm;
    float* hb0 = sm + SM_HB;
    float* hb1 = hb0 + BPG * HH;
    float* red = sm + SM_RED;
    uint64_t* mbar = reinterpret_cast<uint64_t*>(sm + SM_MBAR);

    uint32_t cg;
    asm("mov.u32 %0, %%cluster_ctarank;" : "=r"(cg));
    const int bg  = blockIdx.x >> 3;
    const int c0  = (int)cg * CPG;
    const int b0  = bg * BPG;
    const int ks  = tid >> 4;
    const int cq  = tid & 15;
    const int ob  = tid >> 6;
    const int oc  = tid & 63;

    const uint32_t mbar_u0 = smem_u32(&mbar[0]);
    const uint32_t mbar_u1 = smem_u32(&mbar[1]);
    const uint32_t hb_u0   = smem_u32(hb0);
    const uint32_t d_hb1 = (uint32_t)(BPG * HH * 4);
    const uint32_t d_m0  = mbar_u0 - hb_u0;

    unsigned* prog_p = &g_prog[bg * GC + (int)cg];

    for (int idx = tid; idx < CPG * (HH / 4); idx += 256) {
        int c  = idx & (CPG - 1);
        int k4 = idx >> 6;
        float4 w = *reinterpret_cast<const float4*>(Whh + (size_t)(c0 + c) * HH + k4 * 4);
        Wt[(k4 * 4 + 0) * CPG + c] = w.x;
        Wt[(k4 * 4 + 1) * CPG + c] = w.y;
        Wt[(k4 * 4 + 2) * CPG + c] = w.z;
        Wt[(k4 * 4 + 3) * CPG + c] = w.w;
    }
    {
        float4* d = reinterpret_cast<float4*>(hb0);
        const float4* s = reinterpret_cast<const float4*>(h0 + (size_t)b0 * HH);
        d[tid]       = s[tid];
        d[tid + 256] = s[tid + 256];
    }
    if (tid == 0) {
        asm volatile("mbarrier.init.shared.b64 [%0], %1;" :: "r"(mbar_u0), "r"(1u) : "memory");
        asm volatile("mbarrier.init.shared.b64 [%0], %1;" :: "r"(mbar_u1), "r"(1u) : "memory");
        asm volatile("mbarrier.arrive.expect_tx.shared.b64 _, [%0], %1;"
                     :: "r"(mbar_u0), "r"((unsigned)STEP_TX) : "memory");
        asm volatile("mbarrier.arrive.expect_tx.shared.b64 _, [%0], %1;"
                     :: "r"(mbar_u1), "r"((unsigned)STEP_TX) : "memory");
    }
    __syncthreads();
    asm volatile("barrier.cluster.arrive.aligned;" ::: "memory");
    asm volatile("barrier.cluster.wait.aligned;"   ::: "memory");

    const uint32_t my_off = (uint32_t)((ob * HH + c0 + oc) * 4);
    uint32_t base[GC];
#pragma unroll
    for (int r = 0; r < GC; ++r)
        asm("mapa.shared::cluster.u32 %0, %1, %2;" : "=r"(base[r]) : "r"(hb_u0), "r"(r));

    const float* xbp = g_xb + (size_t)(b0 + ob) * HH + c0 + oc;
    float* outp = use_g0out ? nullptr
                            : out_param + (size_t)(b0 + ob) * TT * HH + c0 + oc;
    __nv_bfloat16* ahip = g_ahi + (size_t)(b0 + ob) * TT * HH + c0 + oc;
    __nv_bfloat16* alop = g_alo + (size_t)(b0 + ob) * TT * HH + c0 + oc;

    uint32_t ph0 = 0, ph1 = 0;

    for (int t = 0; t < TT; ++t) {
        const int p = t & 1;
        float xbv = __ldcg(xbp);
        xbp += BB * HH;

        if (t > 0) {
            if (p) { mbar_wait(mbar_u1, ph1); ph1 ^= 1; }
            else   { mbar_wait(mbar_u0, ph0); ph0 ^= 1; }
            if (tid == 0) {
                uint32_t mu = p ? mbar_u1 : mbar_u0;
                asm volatile("mbarrier.arrive.expect_tx.shared.b64 _, [%0], %1;"
                             :: "r"(mu), "r"((unsigned)STEP_TX) : "memory");
            }
        }

        const float* hb = p ? hb1 : hb0;

        float acc[4][4];
#pragma unroll
        for (int i = 0; i < 4; i++)
#pragma unroll
            for (int j = 0; j < 4; j++) acc[i][j] = 0.f;

        const int kb = ks * 32;
#pragma unroll
        for (int kc = 0; kc < 32; kc += 4) {
            const int k = kb + kc;
            float4 hv[4];
#pragma unroll
            for (int b = 0; b < 4; b++)
                hv[b] = *reinterpret_cast<const float4*>(&hb[b * HH + k]);
#pragma unroll
            for (int kk = 0; kk < 4; kk++) {
                float4 w4 = *reinterpret_cast<const float4*>(&Wt[(k + kk) * CPG + cq * 4]);
                float wj[4] = {w4.x, w4.y, w4.z, w4.w};
                float hk[4] = {hv[0].x, hv[1].x, hv[2].x, hv[3].x};
                if (kk == 1) { hk[0]=hv[0].y; hk[1]=hv[1].y; hk[2]=hv[2].y; hk[3]=hv[3].y; }
                if (kk == 2) { hk[0]=hv[0].z; hk[1]=hv[1].z; hk[2]=hv[2].z; hk[3]=hv[3].z; }
                if (kk == 3) { hk[0]=hv[0].w; hk[1]=hv[1].w; hk[2]=hv[2].w; hk[3]=hv[3].w; }
#pragma unroll
                for (int b = 0; b < 4; b++)
#pragma unroll
                    for (int j = 0; j < 4; j++)
                        acc[b][j] += hk[b] * wj[j];
            }
        }

#pragma unroll
        for (int b = 0; b < 4; ++b)
            *reinterpret_cast<float4*>(&red[ks * 256 + b * 64 + cq * 4]) =
                make_float4(acc[b][0], acc[b][1], acc[b][2], acc[b][3]);
        __syncthreads();   // S1 — orders all step-(t-1) output stores CTA-wide

        // Publish progress (layer 0 only): steps 0..t-1 globally visible.
        if (use_g0out && tid == 0 && t > 0) {
            asm volatile("fence.acq_rel.gpu;" ::: "memory");
            asm volatile("st.release.gpu.global.u32 [%0], %1;"
                         :: "l"(prog_p), "r"((unsigned)t) : "memory");
        }

        float s = 0.f;
#pragma unroll
        for (int k2 = 0; k2 < 16; ++k2) s += red[k2 * 256 + tid];
        float v = tanhf(s + xbv);

        // Sends FIRST (critical path).
        if (t < TT - 1) {
            const uint32_t vb    = __float_as_uint(v);
            const uint32_t d_dst = (p ? 0u : d_hb1) + my_off;
            const uint32_t d_mbr = d_m0 + (p ? 0u : 8u);
#pragma unroll
            for (int r = 0; r < GC; r++) {
                asm volatile(
                    "st.async.shared::cluster.mbarrier::complete_tx::bytes.b32 [%0], %1, [%2];"
                    :: "r"(base[r] + d_dst), "r"(vb), "r"(base[r] + d_mbr) : "memory");
            }
        }

        if (use_g0out) {
            __nv_bfloat16 hb16 = __float2bfloat16_rn(v);
            ahip[(size_t)t * HH] = hb16;
            alop[(size_t)t * HH] = __float2bfloat16_rn(v - __bfloat162float(hb16));
        } else {
            outp[(size_t)t * HH] = v;
        }
        if (t == TT - 1) hn[(size_t)(b0 + ob) * HH + c0 + oc] = v;
    }

    // Final publish + done signal.
    __syncthreads();
    if (use_g0out && tid == 0) {
        asm volatile("fence.acq_rel.gpu;" ::: "memory");
        asm volatile("st.release.gpu.global.u32 [%0], %1;"
                     :: "l"(prog_p), "r"((unsigned)TT) : "memory");
        atomicAdd(&g_done, 1u);
    }

    asm volatile("barrier.cluster.arrive.aligned;" ::: "memory");
    asm volatile("barrier.cluster.wait.aligned;"   ::: "memory");
}

// ------------------------------ launch --------------------------------------
extern "C" void kernel_launch(void* const* d_in, const int* in_sizes, int n_in,
                              void* d_out, int out_size)
{
    const float* x    = (const float*)d_in[0];
    const float* h0   = (const float*)d_in[1];
    const float* Wih0 = (const float*)d_in[2];
    const float* Whh0 = (const float*)d_in[3];
    const float* bih0 = (const float*)d_in[4];
    const float* bhh0 = (const float*)d_in[5];
    const float* Wih1 = (const float*)d_in[6];
    const float* Whh1 = (const float*)d_in[7];
    const float* bih1 = (const float*)d_in[8];
    const float* bhh1 = (const float*)d_in[9];

    float* out  = (float*)d_out;
    float* out1 = out;
    float* hn0  = out + (size_t)BTH;
    float* hn1  = hn0 + (size_t)BB * HH;

    static int inited = 0;
    if (!inited) {
        cudaFuncSetAttribute(rec_fused, cudaFuncAttributeMaxDynamicSharedMemorySize,
                             REC_SMEM_BYTES);
        inited = 1;
    }

    __nv_bfloat16 *whi0, *wlo0, *whi1, *wlo1;
    cudaGetSymbolAddress((void**)&whi0, g_whi0);
    cudaGetSymbolAddress((void**)&wlo0, g_wlo0);
    cudaGetSymbolAddress((void**)&whi1, g_whi1);
    cudaGetSymbolAddress((void**)&wlo1, g_wlo1);

    dim3 ggrid(HH / 64, (BB * TT) / 64);     // (8, 512)

    // Weight splits + counter reset (single stream, strictly ordered).
    conv_split<<<(HH*IDIM + 255)/256, 256>>>(Wih0, whi0, wlo0, HH*IDIM, 1);
    conv_split<<<(HH*HH + 255)/256, 256>>>(Wih1, whi1, wlo1, HH*HH, 0);

    // Layer-0 input projection.
    gemm_wmma<<<ggrid, 256>>>(x, whi0, wlo0, bih0, bhh0, IDIM);

    // rec0 + in-grid gemm1 workers (16 rec clusters + 2 worker clusters).
    rec_fused<<<NCTA + NWORK, THR, REC_SMEM_BYTES>>>(
        Whh0, h0, out1, hn0, 1, bih1, bhh1);

    // Drain any gemm1 tiles the in-grid workers didn't reach.
    gemm1_cleanup<<<512, 256>>>(bih1, bhh1);

    // rec1 (no workers).
    rec_fused<<<NCTA, THR, REC_SMEM_BYTES>>>(
        Whh1, h0 + (size_t)BB * HH, out1, hn1, 0, nullptr, nullptr);
}

// round 14
// speedup vs baseline: 1.2321x; 1.2321x over previous
#include <cuda_runtime.h>
#include <cuda_bf16.h>
#include <mma.h>
#include <cstdint>

using namespace nvcuda;

// Problem dims (fixed)
#define BB   64
#define TT   512
#define IDIM 256
#define HH   512
#define BTH  (BB*TT*HH)

// Recurrence decomposition: 16 clusters (batch groups) x 8 CTAs (column groups)
#define GB   16
#define GC   8
#define BPG  4
#define CPG  64
#define NCTA (GB*GC)
#define THR  256

// ------------------------------ scratch ------------------------------------
__device__ float g_xb[TT*BB*HH];              // input projection [t][b][h]
__device__ __nv_bfloat16 g_ahi[BTH];          // layer-0 output, split hi
__device__ __nv_bfloat16 g_alo[BTH];          // layer-0 output, split lo
__device__ __nv_bfloat16 g_whi0[HH*IDIM];
__device__ __nv_bfloat16 g_wlo0[HH*IDIM];
__device__ __nv_bfloat16 g_whi1[HH*HH];
__device__ __nv_bfloat16 g_wlo1[HH*HH];

// ------------------------------ merged weight split --------------------------
// One launch splits BOTH weight matrices: blocks [0, nb0) handle W0,
// blocks [nb0, nb0+nb1) handle W1.
__global__ void conv_split2(const float* __restrict__ s0, int n0, int nb0,
                            const float* __restrict__ s1, int n1)
{
    const int b = blockIdx.x;
    if (b < nb0) {
        int i = b * 256 + threadIdx.x;
        if (i < n0) {
            float x = s0[i];
            __nv_bfloat16 h = __float2bfloat16_rn(x);
            g_whi0[i] = h;
            g_wlo0[i] = __float2bfloat16_rn(x - __bfloat162float(h));
        }
    } else {
        int i = (b - nb0) * 256 + threadIdx.x;
        if (i < n1) {
            float x = s1[i];
            __nv_bfloat16 h = __float2bfloat16_rn(x);
            g_whi1[i] = h;
            g_wlo1[i] = __float2bfloat16_rn(x - __bfloat162float(h));
        }
    }
}

// ------------------------------ wmma GEMM (bf16 x3 split) --------------------
// Y[t][b][n] = sum_k A[m][k]*W[n][k] + b1[n] + b2[n],  m = b*TT + t
// amode 0: A read as fp32 (Afp), hi/lo split during smem staging.
// amode 1: A read from pre-split bf16 arrays (Ah/Al).
#define KC   64
#define LDS2 72

__device__ __forceinline__ void split16_store(
    const float* __restrict__ srcf, __nv_bfloat16* dH16, __nv_bfloat16* dL16)
{
    const float4* src = reinterpret_cast<const float4*>(srcf);
    float v[16];
#pragma unroll
    for (int j = 0; j < 4; ++j) {
        float4 f = src[j];
        v[j*4+0] = f.x; v[j*4+1] = f.y; v[j*4+2] = f.z; v[j*4+3] = f.w;
    }
    uint32_t ph[8], pl[8];
#pragma unroll
    for (int i = 0; i < 8; ++i) {
        __nv_bfloat16 h0b = __float2bfloat16_rn(v[2*i]);
        __nv_bfloat16 h1b = __float2bfloat16_rn(v[2*i+1]);
        __nv_bfloat16 l0b = __float2bfloat16_rn(v[2*i]   - __bfloat162float(h0b));
        __nv_bfloat16 l1b = __float2bfloat16_rn(v[2*i+1] - __bfloat162float(h1b));
        ph[i] = (uint32_t)__bfloat16_as_ushort(h0b) |
                ((uint32_t)__bfloat16_as_ushort(h1b) << 16);
        pl[i] = (uint32_t)__bfloat16_as_ushort(l0b) |
                ((uint32_t)__bfloat16_as_ushort(l1b) << 16);
    }
    uint4* dH = reinterpret_cast<uint4*>(dH16);
    uint4* dL = reinterpret_cast<uint4*>(dL16);
    dH[0] = make_uint4(ph[0],ph[1],ph[2],ph[3]);
    dH[1] = make_uint4(ph[4],ph[5],ph[6],ph[7]);
    dL[0] = make_uint4(pl[0],pl[1],pl[2],pl[3]);
    dL[1] = make_uint4(pl[4],pl[5],pl[6],pl[7]);
}

__global__ void __launch_bounds__(256) gemm_wmma(
    const float* __restrict__ Afp,
    const __nv_bfloat16* __restrict__ Ah, const __nv_bfloat16* __restrict__ Al,
    const __nv_bfloat16* __restrict__ Bh, const __nv_bfloat16* __restrict__ Bl,
    const float* __restrict__ b1, const float* __restrict__ b2,
    int K, int amode)
{
    __shared__ char raw[4 * 64 * LDS2 * 2];   // 36864 B
    __nv_bfloat16* sAh = reinterpret_cast<__nv_bfloat16*>(raw);
    __nv_bfloat16* sAl = sAh + 64 * LDS2;
    __nv_bfloat16* sBh = sAl + 64 * LDS2;
    __nv_bfloat16* sBl = sBh + 64 * LDS2;

    const int tid = threadIdx.x;
    const int nb  = blockIdx.x;
    const int mb  = blockIdx.y;
    const int wid = tid >> 5;
    const int wr  = wid & 3;
    const int wc  = wid >> 2;

    wmma::fragment<wmma::accumulator, 16, 16, 16, float> acc[2];
    wmma::fill_fragment(acc[0], 0.0f);
    wmma::fill_fragment(acc[1], 0.0f);

    const int row = tid >> 2;            // 0..63
    const int seg = (tid & 3) * 16;      // 16 elems per thread

    for (int k0 = 0; k0 < K; k0 += KC) {
        __syncthreads();
        // ---- stage A ----
        if (amode == 0) {
            split16_store(Afp + (size_t)(mb*64 + row)*K + k0 + seg,
                          sAh + row*LDS2 + seg, sAl + row*LDS2 + seg);
        } else {
            const uint4* a_h = reinterpret_cast<const uint4*>(Ah + (size_t)(mb*64 + row)*K + k0 + seg);
            const uint4* a_l = reinterpret_cast<const uint4*>(Al + (size_t)(mb*64 + row)*K + k0 + seg);
            uint4* dH = reinterpret_cast<uint4*>(sAh + row*LDS2 + seg);
            uint4* dL = reinterpret_cast<uint4*>(sAl + row*LDS2 + seg);
            dH[0] = a_h[0]; dH[1] = a_h[1];
            dL[0] = a_l[0]; dL[1] = a_l[1];
        }
        // ---- stage B (pre-split weights) ----
        {
            const uint4* b_h = reinterpret_cast<const uint4*>(Bh + (size_t)(nb*64 + row)*K + k0 + seg);
            const uint4* b_l = reinterpret_cast<const uint4*>(Bl + (size_t)(nb*64 + row)*K + k0 + seg);
            uint4* dH = reinterpret_cast<uint4*>(sBh + row*LDS2 + seg);
            uint4* dL = reinterpret_cast<uint4*>(sBl + row*LDS2 + seg);
            dH[0] = b_h[0]; dH[1] = b_h[1];
            dL[0] = b_l[0]; dL[1] = b_l[1];
        }
        __syncthreads();

#pragma unroll
        for (int kk = 0; kk < KC / 16; ++kk) {
            wmma::fragment<wmma::matrix_a, 16, 16, 16, __nv_bfloat16, wmma::row_major> fa_h, fa_l;
            wmma::load_matrix_sync(fa_h, sAh + (wr*16)*LDS2 + kk*16, LDS2);
            wmma::load_matrix_sync(fa_l, sAl + (wr*16)*LDS2 + kk*16, LDS2);
#pragma unroll
            for (int ns = 0; ns < 2; ++ns) {
                wmma::fragment<wmma::matrix_b, 16, 16, 16, __nv_bfloat16, wmma::col_major> fb_h, fb_l;
                wmma::load_matrix_sync(fb_h, sBh + (wc*32 + ns*16)*LDS2 + kk*16, LDS2);
                wmma::load_matrix_sync(fb_l, sBl + (wc*32 + ns*16)*LDS2 + kk*16, LDS2);
                wmma::mma_sync(acc[ns], fa_h, fb_h, acc[ns]);
                wmma::mma_sync(acc[ns], fa_h, fb_l, acc[ns]);
                wmma::mma_sync(acc[ns], fa_l, fb_h, acc[ns]);
            }
        }
    }

    __syncthreads();
    float* Cs = reinterpret_cast<float*>(raw);
    wmma::store_matrix_sync(Cs + (wr*16)*LDS2 + wc*32 + 0,  acc[0], LDS2, wmma::mem_row_major);
    wmma::store_matrix_sync(Cs + (wr*16)*LDS2 + wc*32 + 16, acc[1], LDS2, wmma::mem_row_major);
    __syncthreads();

    const int col4 = (tid & 15) * 4;
    const int n0   = nb * 64 + col4;
    float4 bias;
    bias.x = b1[n0 + 0] + b2[n0 + 0];
    bias.y = b1[n0 + 1] + b2[n0 + 1];
    bias.z = b1[n0 + 2] + b2[n0 + 2];
    bias.w = b1[n0 + 3] + b2[n0 + 3];

#pragma unroll
    for (int rr = 0; rr < 4; ++rr) {
        int r  = rr * 16 + (tid >> 4);
        int m  = mb * 64 + r;
        int b_ = m >> 9;
        int t_ = m & (TT - 1);
        float4 o;
        o.x = Cs[r * LDS2 + col4 + 0] + bias.x;
        o.y = Cs[r * LDS2 + col4 + 1] + bias.y;
        o.z = Cs[r * LDS2 + col4 + 2] + bias.z;
        o.w = Cs[r * LDS2 + col4 + 3] + bias.w;
        *reinterpret_cast<float4*>(&g_xb[((size_t)t_ * BB + b_) * HH + n0]) = o;
    }
}

// ------------------------------ helpers -------------------------------------
__device__ __forceinline__ uint32_t smem_u32(const void* p) {
    uint32_t a;
    asm("{ .reg .u64 t; cvta.to.shared.u64 t, %1; cvt.u32.u64 %0, t; }"
        : "=r"(a) : "l"(p));
    return a;
}

__device__ __forceinline__ void mbar_wait(uint32_t mbar, uint32_t parity) {
    asm volatile(
        "{\n\t"
        ".reg .pred P;\n\t"
        "WL%=:\n\t"
        "mbarrier.try_wait.parity.acquire.cluster.shared::cta.b64 P, [%0], %1;\n\t"
        "@!P bra WL%=;\n\t"
        "}"
        :: "r"(mbar), "r"(parity) : "memory");
}

// ------------------------------ recurrence (proven 1396us core) -------------
#define SM_W    (HH*CPG)
#define SM_HB   (SM_W)
#define SM_RED  (SM_W + 2*BPG*HH)
#define SM_MBAR (SM_RED + 16*256)
#define REC_SMEM_BYTES ((SM_MBAR + 8) * 4)

#define STEP_TX (GC * 256 * 4)

__global__ void __launch_bounds__(THR, 1) __cluster_dims__(GC, 1, 1)
rnn_rec(const float* __restrict__ Whh,
        const float* __restrict__ h0,
        float* __restrict__ out_param,
        float* __restrict__ hn,
        int use_g0out)
{
    extern __shared__ float sm[];
    float* Wt  = sm;
    float* hb0 = sm + SM_HB;
    float* hb1 = hb0 + BPG * HH;
    float* red = sm + SM_RED;
    uint64_t* mbar = reinterpret_cast<uint64_t*>(sm + SM_MBAR);

    const int tid = threadIdx.x;
    uint32_t cg;
    asm("mov.u32 %0, %%cluster_ctarank;" : "=r"(cg));
    const int bg  = blockIdx.x >> 3;
    const int c0  = (int)cg * CPG;
    const int b0  = bg * BPG;
    const int ks  = tid >> 4;
    const int cq  = tid & 15;
    const int ob  = tid >> 6;
    const int oc  = tid & 63;

    const uint32_t mbar_u0 = smem_u32(&mbar[0]);
    const uint32_t mbar_u1 = smem_u32(&mbar[1]);
    const uint32_t hb_u0   = smem_u32(hb0);
    const uint32_t hb_u1   = smem_u32(hb1);

    for (int idx = tid; idx < CPG * (HH / 4); idx += 256) {
        int c  = idx & (CPG - 1);
        int k4 = idx >> 6;
        float4 w = *reinterpret_cast<const float4*>(Whh + (size_t)(c0 + c) * HH + k4 * 4);
        Wt[(k4 * 4 + 0) * CPG + c] = w.x;
        Wt[(k4 * 4 + 1) * CPG + c] = w.y;
        Wt[(k4 * 4 + 2) * CPG + c] = w.z;
        Wt[(k4 * 4 + 3) * CPG + c] = w.w;
    }
    {
        float4* d = reinterpret_cast<float4*>(hb0);
        const float4* s = reinterpret_cast<const float4*>(h0 + (size_t)b0 * HH);
        d[tid]       = s[tid];
        d[tid + 256] = s[tid + 256];
    }
    if (tid == 0) {
        asm volatile("mbarrier.init.shared.b64 [%0], %1;" :: "r"(mbar_u0), "r"(1u) : "memory");
        asm volatile("mbarrier.init.shared.b64 [%0], %1;" :: "r"(mbar_u1), "r"(1u) : "memory");
        asm volatile("mbarrier.arrive.expect_tx.shared.b64 _, [%0], %1;"
                     :: "r"(mbar_u0), "r"((unsigned)STEP_TX) : "memory");
        asm volatile("mbarrier.arrive.expect_tx.shared.b64 _, [%0], %1;"
                     :: "r"(mbar_u1), "r"((unsigned)STEP_TX) : "memory");
    }
    __syncthreads();
    asm volatile("barrier.cluster.arrive.aligned;" ::: "memory");
    asm volatile("barrier.cluster.wait.aligned;"   ::: "memory");

    uint32_t ph0 = 0, ph1 = 0;
    const uint32_t my_off = (uint32_t)((ob * HH + c0 + oc) * 4);

    for (int t = 0; t < TT; ++t) {
        const int p = t & 1;
        float xbv = __ldcg(&g_xb[((size_t)t * BB + (b0 + ob)) * HH + c0 + oc]);

        if (t > 0) {
            if (p) { mbar_wait(mbar_u1, ph1); ph1 ^= 1; }
            else   { mbar_wait(mbar_u0, ph0); ph0 ^= 1; }
            if (tid == 0) {
                uint32_t mu = p ? mbar_u1 : mbar_u0;
                asm volatile("mbarrier.arrive.expect_tx.shared.b64 _, [%0], %1;"
                             :: "r"(mu), "r"((unsigned)STEP_TX) : "memory");
            }
        }

        const float* hb = p ? hb1 : hb0;

        float acc[4][4];
#pragma unroll
        for (int i = 0; i < 4; i++)
#pragma unroll
            for (int j = 0; j < 4; j++) acc[i][j] = 0.f;

        const int kb = ks * 32;
#pragma unroll
        for (int kc = 0; kc < 32; kc += 4) {
            const int k = kb + kc;
            float4 hv[4];
#pragma unroll
            for (int b = 0; b < 4; b++)
                hv[b] = *reinterpret_cast<const float4*>(&hb[b * HH + k]);
#pragma unroll
            for (int kk = 0; kk < 4; kk++) {
                float4 w4 = *reinterpret_cast<const float4*>(&Wt[(k + kk) * CPG + cq * 4]);
                float wj[4] = {w4.x, w4.y, w4.z, w4.w};
                float hk[4] = {hv[0].x, hv[1].x, hv[2].x, hv[3].x};
                if (kk == 1) { hk[0]=hv[0].y; hk[1]=hv[1].y; hk[2]=hv[2].y; hk[3]=hv[3].y; }
                if (kk == 2) { hk[0]=hv[0].z; hk[1]=hv[1].z; hk[2]=hv[2].z; hk[3]=hv[3].z; }
                if (kk == 3) { hk[0]=hv[0].w; hk[1]=hv[1].w; hk[2]=hv[2].w; hk[3]=hv[3].w; }
#pragma unroll
                for (int b = 0; b < 4; b++)
#pragma unroll
                    for (int j = 0; j < 4; j++)
                        acc[b][j] += hk[b] * wj[j];
            }
        }

#pragma unroll
        for (int b = 0; b < 4; ++b)
            *reinterpret_cast<float4*>(&red[ks * 256 + b * 64 + cq * 4]) =
                make_float4(acc[b][0], acc[b][1], acc[b][2], acc[b][3]);
        __syncthreads();   // S1

        float s = 0.f;
#pragma unroll
        for (int k2 = 0; k2 < 16; ++k2) s += red[k2 * 256 + tid];
        float v = tanhf(s + xbv);

        const size_t oidx = ((size_t)(b0 + ob) * TT + t) * HH + c0 + oc;
        if (use_g0out) {
            __nv_bfloat16 hb16 = __float2bfloat16_rn(v);
            g_ahi[oidx] = hb16;
            g_alo[oidx] = __float2bfloat16_rn(v - __bfloat162float(hb16));
        } else {
            out_param[oidx] = v;
        }
        if (t == TT - 1) hn[(size_t)(b0 + ob) * HH + c0 + oc] = v;

        if (t < TT - 1) {
            const uint32_t dst_l  = (p ? hb_u0 : hb_u1) + my_off;
            const uint32_t mbar_l = p ? mbar_u0 : mbar_u1;
            const uint32_t vb = __float_as_uint(v);
#pragma unroll
            for (int r = 0; r < GC; r++) {
                uint32_t da, ma;
                asm("mapa.shared::cluster.u32 %0, %1, %2;" : "=r"(da) : "r"(dst_l),  "r"(r));
                asm("mapa.shared::cluster.u32 %0, %1, %2;" : "=r"(ma) : "r"(mbar_l), "r"(r));
                asm volatile(
                    "st.async.shared::cluster.mbarrier::complete_tx::bytes.b32 [%0], %1, [%2];"
                    :: "r"(da), "r"(vb), "r"(ma) : "memory");
            }
        }
    }

    asm volatile("barrier.cluster.arrive.aligned;" ::: "memory");
    asm volatile("barrier.cluster.wait.aligned;"   ::: "memory");
}

// ------------------------------ launch --------------------------------------
extern "C" void kernel_launch(void* const* d_in, const int* in_sizes, int n_in,
                              void* d_out, int out_size)
{
    const float* x    = (const float*)d_in[0];
    const float* h0   = (const float*)d_in[1];
    const float* Wih0 = (const float*)d_in[2];
    const float* Whh0 = (const float*)d_in[3];
    const float* bih0 = (const float*)d_in[4];
    const float* bhh0 = (const float*)d_in[5];
    const float* Wih1 = (const float*)d_in[6];
    const float* Whh1 = (const float*)d_in[7];
    const float* bih1 = (const float*)d_in[8];
    const float* bhh1 = (const float*)d_in[9];

    float* out  = (float*)d_out;
    float* out1 = out;                       // [B,T,H]
    float* hn0  = out + (size_t)BTH;
    float* hn1  = hn0 + (size_t)BB * HH;

    static int smem_set = 0;
    if (!smem_set) {
        cudaFuncSetAttribute(rnn_rec, cudaFuncAttributeMaxDynamicSharedMemorySize,
                             REC_SMEM_BYTES);
        smem_set = 1;
    }

    __nv_bfloat16 *ahi, *alo, *whi0, *wlo0, *whi1, *wlo1;
    cudaGetSymbolAddress((void**)&ahi,  g_ahi);
    cudaGetSymbolAddress((void**)&alo,  g_alo);
    cudaGetSymbolAddress((void**)&whi0, g_whi0);
    cudaGetSymbolAddress((void**)&wlo0, g_wlo0);
    cudaGetSymbolAddress((void**)&whi1, g_whi1);
    cudaGetSymbolAddress((void**)&wlo1, g_wlo1);

    dim3 ggrid(HH / 64, (BB * TT) / 64);     // (8, 512)

    // Single merged weight-split launch (W0: 512 blocks, W1: 1024 blocks).
    const int nb0 = (HH * IDIM + 255) / 256;
    const int nb1 = (HH * HH + 255) / 256;
    conv_split2<<<nb0 + nb1, 256>>>(Wih0, HH * IDIM, nb0, Wih1, HH * HH);

    // ---- layer 0 ----
    gemm_wmma<<<ggrid, 256>>>(x, nullptr, nullptr, whi0, wlo0, bih0, bhh0, IDIM, 0);
    rnn_rec<<<NCTA, THR, REC_SMEM_BYTES>>>(Whh0, h0, out1, hn0, 1);

    // ---- layer 1 ----
    gemm_wmma<<<ggrid, 256>>>(nullptr, ahi, alo, whi1, wlo1, bih1, bhh1, HH, 1);
    rnn_rec<<<NCTA, THR, REC_SMEM_BYTES>>>(Whh1, h0 + (size_t)BB * HH, out1, hn1, 0);
}